// round 12
// baseline (speedup 1.0000x reference)
#include <cuda_runtime.h>
#include <cuda_bf16.h>

// ROIRotate: bilinear crop-and-resize of axis-aligned boxes from an NHWC
// feature map.
//
// Shapes (static):
//   feature_map: (8, 128, 128, 32) fp32  (~16.7 MB, L2-resident)
//   boxes:       (2048, 9) fp32
//   box_indices: (2048,) int32 (harness downcasts the reference's int64)
//   max_width:   64
// Output: crops (2048, 8, 64, 32) fp32 + padded_width (2048,) fp32, flat.
//
// Kernel 1 (box_prep): per-box math -> 8-float param block + padded_width.
// Kernel 2 (main): ILP-2 over u. Each thread produces two adjacent u
//   positions (same box/v/quad): 8 gathers in flight, math amortized,
//   optimal L1 wavefronts (4 gather + 1 store per position), coalesced
//   128B stores, __stcs to keep the feature map L2-resident.

#define ROI_HEIGHT 8
#define ROI_MAXW   64
#define ROI_NBOX   2048
#define FM_N       8
#define FM_H       128
#define FM_W       128
#define FM_C       32

// Per-box param block: {x1, y1, du_x, du_y, dv_x, dv_y, width, n_as_float_bits}
__device__ __align__(32) float g_boxparams[ROI_NBOX * 8];

__global__ void box_prep_kernel(const float* __restrict__ boxes,
                                const int* __restrict__ bidx,
                                float* __restrict__ out)
{
    int b = blockIdx.x * blockDim.x + threadIdx.x;
    if (b >= ROI_NBOX) return;

    const float* bp = boxes + b * 9;
    float x1 = bp[0] * 0.25f, y1 = bp[1] * 0.25f;
    float x2 = bp[2] * 0.25f, y2 = bp[3] * 0.25f;
    float x4 = bp[6] * 0.25f, y4 = bp[7] * 0.25f;

    float box_w = x2 - x1;
    float box_h = y4 - y1;
    float width = (float)ROI_HEIGHT * box_w / fmaxf(box_h, 1e-6f);
    width = fminf(fmaxf(width, 1.0f), (float)ROI_MAXW);
    float inv_w = 1.0f / width;

    float* p = g_boxparams + b * 8;
    float4 p0 = make_float4(x1, y1, (x2 - x1) * inv_w, (y2 - y1) * inv_w);
    float4 p1 = make_float4((x4 - x1) * (1.0f / ROI_HEIGHT),
                            (y4 - y1) * (1.0f / ROI_HEIGHT),
                            width,
                            __int_as_float(bidx[b]));
    *(float4*)(p)     = p0;
    *(float4*)(p + 4) = p1;

    out[(size_t)ROI_NBOX * ROI_HEIGHT * ROI_MAXW * FM_C + b] =
        (float)ROI_MAXW - width;
}

// One bilinear sample: given row base pointers and x indices + weights.
__device__ __forceinline__ float4 bilerp(const float* __restrict__ row0,
                                         const float* __restrict__ row1,
                                         int x0i, int x1i,
                                         float wx, float wy)
{
    float4 g00 = *(const float4*)(row0 + ((size_t)x0i << 5));
    float4 g01 = *(const float4*)(row0 + ((size_t)x1i << 5));
    float4 g10 = *(const float4*)(row1 + ((size_t)x0i << 5));
    float4 g11 = *(const float4*)(row1 + ((size_t)x1i << 5));

    float w00 = (1.f - wy) * (1.f - wx);
    float w01 = (1.f - wy) * wx;
    float w10 = wy * (1.f - wx);
    float w11 = wy * wx;

    float4 r;
    r.x = fmaf(w00, g00.x, fmaf(w01, g01.x, fmaf(w10, g10.x, w11 * g11.x)));
    r.y = fmaf(w00, g00.y, fmaf(w01, g01.y, fmaf(w10, g10.y, w11 * g11.y)));
    r.z = fmaf(w00, g00.z, fmaf(w01, g01.z, fmaf(w10, g10.z, w11 * g11.z)));
    r.w = fmaf(w00, g00.w, fmaf(w01, g01.w, fmaf(w10, g10.w, w11 * g11.w)));
    return r;
}

// threads: one per (box, v, u-pair, channel-quad).
// total = 2048 * 8 * 32 * 8 = 4,194,304
__global__ __launch_bounds__(256)
void roi_rotate_kernel(const float* __restrict__ fm,
                       float* __restrict__ out)
{
    int gid  = blockIdx.x * blockDim.x + threadIdx.x;
    int quad = gid & 7;                 // channel quad 0..7 (16 B)
    int t    = gid >> 3;
    int uh   = t & (ROI_MAXW / 2 - 1);  // u-pair index 0..31
    int bv   = t >> 5;
    int v    = bv & (ROI_HEIGHT - 1);
    int b    = bv >> 3;

    const float* p = g_boxparams + b * 8;
    float4 p0 = *(const float4*)(p);      // x1, y1, du_x, du_y
    float4 p1 = *(const float4*)(p + 4);  // dv_x, dv_y, width, n bits

    float u0f = (float)(uh << 1);
    float u1f = u0f + 1.0f;
    float vf  = (float)v;

    int n  = __float_as_int(p1.w);
    int co = quad << 2;   // 4 floats = 16 B per lane
    const float* fmn = fm + (((size_t)n * FM_H * FM_W) << 5) + co;

    // Base sample coords at u0; u1 = u0 + du
    float bx = fmaf(vf, p1.x, p0.x);
    float by = fmaf(vf, p1.y, p0.y);

    float4 rA = make_float4(0.f, 0.f, 0.f, 0.f);
    float4 rB = make_float4(0.f, 0.f, 0.f, 0.f);

    if (u0f < p1.z) {
        float sx = fmaf(u0f, p0.z, bx);
        float sy = fmaf(u0f, p0.w, by);
        float fx0 = floorf(sx), fy0 = floorf(sy);
        float wx = sx - fx0,    wy = sy - fy0;
        int x0i = min(max((int)fx0, 0), FM_W - 1);
        int x1i = min(x0i + 1, FM_W - 1);
        int y0i = min(max((int)fy0, 0), FM_H - 1);
        int y1i = min(y0i + 1, FM_H - 1);
        const float* row0 = fmn + (((size_t)y0i * FM_W) << 5);
        const float* row1 = fmn + (((size_t)y1i * FM_W) << 5);
        rA = bilerp(row0, row1, x0i, x1i, wx, wy);
    }

    if (u1f < p1.z) {
        float sx = fmaf(u1f, p0.z, bx);
        float sy = fmaf(u1f, p0.w, by);
        float fx0 = floorf(sx), fy0 = floorf(sy);
        float wx = sx - fx0,    wy = sy - fy0;
        int x0i = min(max((int)fx0, 0), FM_W - 1);
        int x1i = min(x0i + 1, FM_W - 1);
        int y0i = min(max((int)fy0, 0), FM_H - 1);
        int y1i = min(y0i + 1, FM_H - 1);
        const float* row0 = fmn + (((size_t)y0i * FM_W) << 5);
        const float* row1 = fmn + (((size_t)y1i * FM_W) << 5);
        rB = bilerp(row0, row1, x0i, x1i, wx, wy);
    }

    // Stores: pos0 = (b,v,2*uh), pos1 = pos0+1. Each warp covers 8
    // consecutive 128B output rows -> fully coalesced streaming stores.
    size_t pos0 = ((size_t)bv << 6) + (size_t)(uh << 1);
    float* dst = out + (pos0 << 5) + co;
    __stcs((float4*)(dst), rA);
    __stcs((float4*)(dst + FM_C), rB);
}

extern "C" void kernel_launch(void* const* d_in, const int* in_sizes, int n_in,
                              void* d_out, int out_size)
{
    const float* fm    = (const float*)d_in[0];
    const float* boxes = (const float*)d_in[1];
    const int*   bidx  = (const int*)d_in[2];
    float*       out   = (float*)d_out;

    box_prep_kernel<<<ROI_NBOX / 256, 256>>>(boxes, bidx, out);

    const int total = ROI_NBOX * ROI_HEIGHT * (ROI_MAXW / 2) * (FM_C / 4); // 4,194,304
    roi_rotate_kernel<<<total / 256, 256>>>(fm, out);
}